// round 7
// baseline (speedup 1.0000x reference)
#include <cuda_runtime.h>

#define G 1024
#define BATCH 4
#define ROWS 20
#define NCHUNK 52              // 51 full chunks of 20 + tail of 3 (51*20+3=1023)
#define NSTRIP 33              // 33 warps * 31 quads = 1023 columns
#define ROWSTRIDE (G * 3)
#define TOTWARPS (NSTRIP * NCHUNK * BATCH)   // 6864
#define NBLOCKS ((TOTWARPS + 7) / 8)         // 858  (one wave @ 6 CTA/SM)

// E = 1023*1023 + 1022*1023 + 1023*1022 = 3,137,541 ; N = B*E
#define N_TOTAL 12550164.0

__device__ double g_acc = 0.0;
__device__ unsigned int g_done = 0;

struct V3 { float x, y, z; };

__device__ __forceinline__ V3 vsub(V3 a, V3 b) {
    V3 r; r.x = a.x - b.x; r.y = a.y - b.y; r.z = a.z - b.z; return r;
}
__device__ __forceinline__ V3 vcross(V3 a, V3 b) {
    V3 r;
    r.x = fmaf(a.y, b.z, -a.z * b.y);
    r.y = fmaf(a.z, b.x, -a.x * b.z);
    r.z = fmaf(a.x, b.y, -a.y * b.x);
    return r;
}
__device__ __forceinline__ float vdot(V3 a, V3 b) {
    return fmaf(a.x, b.x, fmaf(a.y, b.y, a.z * b.z));
}
__device__ __forceinline__ float rq(V3 a) {            // rsqrt(max(|a|^2, eps^2))
    return rsqrtf(fmaxf(vdot(a, a), 1e-16f));
}
__device__ __forceinline__ V3 vscale(V3 a, float s) {
    V3 r; r.x = a.x * s; r.y = a.y * s; r.z = a.z * s; return r;
}
__device__ __forceinline__ V3 ldv(const float* __restrict__ p) {
    V3 r; r.x = p[0]; r.y = p[1]; r.z = p[2]; return r;
}
__device__ __forceinline__ V3 shup(V3 v) {
    V3 r;
    r.x = __shfl_up_sync(0xFFFFFFFFu, v.x, 1);
    r.y = __shfl_up_sync(0xFFFFFFFFu, v.y, 1);
    r.z = __shfl_up_sync(0xFFFFFFFFu, v.z, 1);
    return r;
}

struct St {
    const float* row;
    V3 p00, p01, u2prev;
    int d3;
    float m_dh, m_v;
};

__device__ __forceinline__ float quad_row(St& s) {
    const float* __restrict__ nrow = s.row + ROWSTRIDE;
    V3 p10 = ldv(nrow);
    V3 p11 = ldv(nrow + s.d3);

    V3 e1 = vsub(s.p01, s.p00);
    V3 e2 = vsub(p10,  s.p00);
    V3 dd = vsub(p11,  s.p00);

    V3 cA = vcross(dd, e1);          // T1 normal (tl,br,tr)
    V3 cB = vcross(e2, dd);          // T2 normal (tl,bl,br)
    V3 u1 = vscale(cA, rq(cA));
    V3 u2 = vscale(cB, rq(cB));

    // diag + horiz (u2prev==0 at global row 0 -> horiz contributes 0)
    float acc = s.m_dh * (vdot(u1, u2) + vdot(u1, s.u2prev));
    // vert: left quad's u1 via shuffle
    V3 u1l = shup(u1);
    acc = fmaf(s.m_v, vdot(u2, u1l), acc);

    s.p00 = p10; s.p01 = p11; s.u2prev = u2; s.row = nrow;
    return acc;
}

__global__ void __launch_bounds__(256, 6)
nc_fused_kernel(const float* __restrict__ x, float* __restrict__ out,
                unsigned int nblocks) {
    const int lane = threadIdx.x & 31;
    const int wid  = threadIdx.x >> 5;
    const int W    = blockIdx.x * 8 + wid;

    float sum = 0.0f;
    if (W < TOTWARPS) {
        const int strip = W % NSTRIP;
        const int rest  = W / NSTRIP;
        const int chunk = rest % NCHUNK;
        const int bb    = rest / NCHUNK;

        const int c  = strip * 31 + lane;       // 0..1023
        const int r0 = chunk * ROWS;
        const bool cvalid = (c < G - 1);        // c <= 1022

        St s;
        s.d3   = cvalid ? 3 : 0;                // invalid lane: clamp to own column
        s.m_dh = (lane < 31) ? 1.0f : 0.0f;     // diag+horiz owner lanes
        s.m_v  = (lane >= 1 && cvalid) ? 1.0f : 0.0f;

        const float* __restrict__ base = x + (size_t)bb * (size_t)G * G * 3;
        s.row = base + ((size_t)r0 * G + c) * 3;
        s.p00 = ldv(s.row);
        s.p01 = ldv(s.row + s.d3);
        s.u2prev = V3{0.f, 0.f, 0.f};
        if (r0 >= 1) {                           // û2 of quad (r0-1, c)
            V3 pm = ldv(s.row - ROWSTRIDE);
            V3 e2p = vsub(s.p00, pm);
            V3 dp  = vsub(s.p01, pm);
            V3 cBp = vcross(e2p, dp);
            s.u2prev = vscale(cBp, rq(cBp));
        }

        const int nrows = min(ROWS, (G - 1) - r0);
        if (nrows == ROWS) {
            #pragma unroll 2
            for (int i = 0; i < ROWS; ++i) sum += quad_row(s);
        } else {
            for (int i = 0; i < nrows; ++i) sum += quad_row(s);
        }
    }

    // ---- block reduction ----
    #pragma unroll
    for (int off = 16; off > 0; off >>= 1)
        sum += __shfl_down_sync(0xFFFFFFFFu, sum, off);

    __shared__ float warp_sums[8];
    if (lane == 0) warp_sums[wid] = sum;
    __syncthreads();

    __shared__ bool is_last;
    if (wid == 0) {
        float sv = (lane < 8) ? warp_sums[lane] : 0.0f;
        #pragma unroll
        for (int off = 4; off > 0; off >>= 1)
            sv += __shfl_down_sync(0xFFFFFFFFu, sv, off);
        if (lane == 0) {
            atomicAdd(&g_acc, (double)sv);
            __threadfence();
            unsigned int done = atomicInc(&g_done, nblocks - 1);
            is_last = (done == nblocks - 1);
        }
    }
    __syncthreads();

    if (is_last && threadIdx.x == 0) {
        double acc = atomicAdd(&g_acc, 0.0);      // coherent read
        out[0] = (float)(1.0 - acc / N_TOTAL);    // loss = 1 - mean(cos)
        __threadfence();
        g_acc = 0.0;                               // g_done wrapped via atomicInc
    }
}

extern "C" void kernel_launch(void* const* d_in, const int* in_sizes, int n_in,
                              void* d_out, int out_size) {
    const float* x = (const float*)d_in[0];
    float* out = (float*)d_out;

    dim3 block(256, 1, 1);
    dim3 grid(NBLOCKS, 1, 1);   // 858 blocks -> one wave @ 6 CTA/SM
    nc_fused_kernel<<<grid, block>>>(x, out, NBLOCKS);
}

// round 8
// speedup vs baseline: 1.0221x; 1.0221x over previous
#include <cuda_runtime.h>

#define G 1024
#define BATCH 4
#define ROWS 16
#define NCHUNK 64              // 63*16=1008, last chunk 15 rows (1023 total)
#define NSTRIP 9               // strips of 124 quads: 8*124+31 = 1023 columns
#define ROWSTRIDE (G * 3)
#define TOTWARPS (NSTRIP * NCHUNK * BATCH)   // 2304
#define NBLOCKS (TOTWARPS / 4)               // 576 blocks of 128 thr (one wave @4 CTA/SM)

// E = 1023*1023 + 1022*1023 + 1023*1022 = 3,137,541 ; N = B*E
#define N_TOTAL 12550164.0

__device__ double g_acc = 0.0;
__device__ unsigned int g_done = 0;

struct V3 { float x, y, z; };

__device__ __forceinline__ V3 vsub(V3 a, V3 b) {
    V3 r; r.x = a.x - b.x; r.y = a.y - b.y; r.z = a.z - b.z; return r;
}
__device__ __forceinline__ V3 vcross(V3 a, V3 b) {
    V3 r;
    r.x = fmaf(a.y, b.z, -a.z * b.y);
    r.y = fmaf(a.z, b.x, -a.x * b.z);
    r.z = fmaf(a.x, b.y, -a.y * b.x);
    return r;
}
__device__ __forceinline__ float vdot(V3 a, V3 b) {
    return fmaf(a.x, b.x, fmaf(a.y, b.y, a.z * b.z));
}
__device__ __forceinline__ float rq(V3 a) {            // rsqrt(max(|a|^2, eps^2))
    return rsqrtf(fmaxf(vdot(a, a), 1e-16f));
}
__device__ __forceinline__ V3 vscale(V3 a, float s) {
    V3 r; r.x = a.x * s; r.y = a.y * s; r.z = a.z * s; return r;
}
__device__ __forceinline__ V3 shup(V3 v) {
    V3 r;
    r.x = __shfl_up_sync(0xFFFFFFFFu, v.x, 1);
    r.y = __shfl_up_sync(0xFFFFFFFFu, v.y, 1);
    r.z = __shfl_up_sync(0xFFFFFFFFu, v.z, 1);
    return r;
}
__device__ __forceinline__ V3 shdn(V3 v) {
    V3 r;
    r.x = __shfl_down_sync(0xFFFFFFFFu, v.x, 1);
    r.y = __shfl_down_sync(0xFFFFFFFFu, v.y, 1);
    r.z = __shfl_down_sync(0xFFFFFFFFu, v.z, 1);
    return r;
}

// Load 4 vertices (12 floats, 16B-aligned) into v[0..3]; v[4] = lane+1's v[0].
__device__ __forceinline__ void load_row(const float* __restrict__ p, V3 v[5]) {
    float4 f0 = *reinterpret_cast<const float4*>(p);
    float4 f1 = *reinterpret_cast<const float4*>(p + 4);
    float4 f2 = *reinterpret_cast<const float4*>(p + 8);
    v[0] = V3{f0.x, f0.y, f0.z};
    v[1] = V3{f0.w, f1.x, f1.y};
    v[2] = V3{f1.z, f1.w, f2.x};
    v[3] = V3{f2.y, f2.z, f2.w};
    v[4] = shdn(v[0]);
}

__global__ void __launch_bounds__(128, 4)
nc_fused_kernel(const float* __restrict__ x, float* __restrict__ out,
                unsigned int nblocks) {
    const int lane = threadIdx.x & 31;
    const int wid  = threadIdx.x >> 5;
    const int W    = blockIdx.x * 4 + wid;

    // warp -> (strip, chunk, batch)
    const int strip = W % NSTRIP;
    const int rest  = W / NSTRIP;
    const int chunk = rest % NCHUNK;
    const int bb    = rest / NCHUNK;

    const int c0    = strip * 124 + 4 * lane;   // first quad column of this thread
    const int cload = min(c0, 1020);            // keep loads in-bounds & 16B-aligned
    const int r0    = chunk * ROWS;
    const int nrows = min(ROWS, (G - 1) - r0);

    // per-quad masks (loop-invariant)
    float mdh[4], mv[4];
    #pragma unroll
    for (int q = 0; q < 4; ++q) {
        bool colv = (c0 + q) <= 1022;
        mdh[q] = (lane < 31 && colv) ? 1.0f : 0.0f;
        mv[q]  = (q == 0) ? ((lane >= 1 && colv) ? 1.0f : 0.0f)
                          : ((lane < 31 && colv) ? 1.0f : 0.0f);
    }

    const float* __restrict__ base = x + (size_t)bb * (size_t)G * G * 3;
    const float* __restrict__ row  = base + ((size_t)r0 * G + cload) * 3;

    V3 o[5], u2p[4];
    if (r0 >= 1) {
        // compute u2 of row r0-1 quads (for the horizontal edges at row r0)
        V3 op[5];
        load_row(row - ROWSTRIDE, op);
        load_row(row, o);
        #pragma unroll
        for (int q = 0; q < 4; ++q) {
            V3 e2 = vsub(o[q],     op[q]);
            V3 dd = vsub(o[q + 1], op[q]);
            V3 cB = vcross(e2, dd);
            u2p[q] = vscale(cB, rq(cB));
        }
    } else {
        load_row(row, o);
        #pragma unroll
        for (int q = 0; q < 4; ++q) u2p[q] = V3{0.f, 0.f, 0.f};
    }

    float sum = 0.0f;
    for (int i = 0; i < nrows; ++i) {
        const float* __restrict__ nrow = row + ROWSTRIDE;
        V3 n[5];
        load_row(nrow, n);

        V3 u1prev;   // u1 of quad q-1 (for local vertical edges)
        #pragma unroll
        for (int q = 0; q < 4; ++q) {
            V3 e1 = vsub(o[q + 1], o[q]);
            V3 e2 = vsub(n[q],     o[q]);
            V3 dd = vsub(n[q + 1], o[q]);
            V3 cA = vcross(dd, e1);          // T1 normal
            V3 cB = vcross(e2, dd);          // T2 normal
            V3 u1 = vscale(cA, rq(cA));
            V3 u2 = vscale(cB, rq(cB));

            // diag + horiz (u2p==0 at global row 0 -> horiz contributes 0)
            sum = fmaf(mdh[q], vdot(u1, u2) + vdot(u1, u2p[q]), sum);
            if (q > 0) sum = fmaf(mv[q], vdot(u2, u1prev), sum);   // local vertical
            u2p[q] = u2;
            u1prev = u1;
        }
        // boundary vertical of quad 0: left neighbor's last u1 (lane-1's u1[3])
        V3 u1l = shup(u1prev);
        sum = fmaf(mv[0], vdot(u2p[0], u1l), sum);

        #pragma unroll
        for (int q = 0; q < 5; ++q) o[q] = n[q];
        row = nrow;
    }

    // ---- block reduction (4 warps) ----
    #pragma unroll
    for (int off = 16; off > 0; off >>= 1)
        sum += __shfl_down_sync(0xFFFFFFFFu, sum, off);

    __shared__ float warp_sums[4];
    if (lane == 0) warp_sums[wid] = sum;
    __syncthreads();

    __shared__ bool is_last;
    if (wid == 0) {
        float sv = (lane < 4) ? warp_sums[lane] : 0.0f;
        #pragma unroll
        for (int off = 2; off > 0; off >>= 1)
            sv += __shfl_down_sync(0xFFFFFFFFu, sv, off);
        if (lane == 0) {
            atomicAdd(&g_acc, (double)sv);
            __threadfence();
            unsigned int done = atomicInc(&g_done, nblocks - 1);
            is_last = (done == nblocks - 1);
        }
    }
    __syncthreads();

    if (is_last && threadIdx.x == 0) {
        double acc = atomicAdd(&g_acc, 0.0);      // coherent read
        out[0] = (float)(1.0 - acc / N_TOTAL);    // loss = 1 - mean(cos)
        __threadfence();
        g_acc = 0.0;                               // g_done wrapped via atomicInc
    }
}

extern "C" void kernel_launch(void* const* d_in, const int* in_sizes, int n_in,
                              void* d_out, int out_size) {
    const float* x = (const float*)d_in[0];
    float* out = (float*)d_out;

    dim3 block(128, 1, 1);
    dim3 grid(NBLOCKS, 1, 1);   // 576 blocks -> one wave @ 4 CTA/SM (128-thr blocks)
    nc_fused_kernel<<<grid, block>>>(x, out, NBLOCKS);
}